// round 16
// baseline (speedup 1.0000x reference)
#include <cuda_runtime.h>
#include <cuda_fp16.h>
#include <math.h>
#include <stdint.h>

#define Bn 256
#define Sn 256
#define Tn 32
#define Hn 512
#define En 128
#define EDn 32
#define An 8
#define NTn 80

__device__ float  g_h[2][Bn*Hn];
__device__ __half g_h16[2][Bn*Hn];
__device__ float  g_c[Bn*Hn];
__device__ float  g_enc_out[(size_t)Sn*Bn*Hn];
__device__ float  g_zx[1000*4*Hn];
__device__ float  g_act_z[An*4*Hn];
__device__ float  g_tgt_z[NTn*4*Hn];
__device__ float  g_P[(size_t)Bn*96*Sn];     // [b][col][s] — s contiguous
__device__ float  g_wpad[128*Hn];
__device__ float  g_wie_r[4*Hn*En];
__device__ __half g_whe_h[4*Hn*Hn];
__device__ __half g_whd_h[4*Hn*Hn];
__device__ float  g_emb_r[1000*En];
__device__ int    g_inp[Bn*2];
__device__ int    g_bar[1152];

__device__ __forceinline__ float sigmoidf_(float x){ return 1.f/(1.f+expf(-x)); }
__device__ __forceinline__ float rna_f(float x){
    uint32_t u; asm("cvt.rna.tf32.f32 %0, %1;" : "=r"(u) : "f"(x));
    return __uint_as_float(u);
}
__device__ __forceinline__ uint32_t smem_u32(const void* p){
    uint32_t a;
    asm("{ .reg .u64 t; cvta.to.shared.u64 t, %1; cvt.u32.u64 %0, t; }" : "=r"(a) : "l"(p));
    return a;
}
#define CP_ASYNC16(dst, src) \
    asm volatile("cp.async.cg.shared.global [%0], [%1], 16;" :: "r"(dst), "l"(src))
#define CP_COMMIT() asm volatile("cp.async.commit_group;" ::: "memory")
#define CP_WAIT(n)  asm volatile("cp.async.wait_group %0;" :: "n"(n) : "memory")
#define MMA_TF32(d, a, b0v, b1v) \
    asm volatile("mma.sync.aligned.m16n8k8.row.col.f32.tf32.tf32.f32 " \
        "{%0,%1,%2,%3}, {%4,%5,%6,%7}, {%8,%9}, {%0,%1,%2,%3};" \
        : "+f"((d)[0]),"+f"((d)[1]),"+f"((d)[2]),"+f"((d)[3]) \
        : "r"((a)[0]),"r"((a)[1]),"r"((a)[2]),"r"((a)[3]), "r"(b0v),"r"(b1v))
#define MMA_F16(d, a0,a1,a2,a3, b0v,b1v) \
    asm volatile("mma.sync.aligned.m16n8k16.row.col.f32.f16.f16.f32 " \
        "{%0,%1,%2,%3}, {%4,%5,%6,%7}, {%8,%9}, {%0,%1,%2,%3};" \
        : "+f"((d)[0]),"+f"((d)[1]),"+f"((d)[2]),"+f"((d)[3]) \
        : "r"(a0),"r"(a1),"r"(a2),"r"(a3), "r"(b0v),"r"(b1v))

__device__ __forceinline__ int sidx(int r, int w){
    return r*32 + ((((w>>2) ^ (r&7)) << 2) | (w&3));
}

__device__ __forceinline__ void gbar(int idx, int nc){
    __syncthreads();
    if (threadIdx.x == 0){
        int* p = &g_bar[idx];
        asm volatile("red.release.gpu.global.add.u32 [%0], 1;" :: "l"(p) : "memory");
        uint32_t v;
        do {
            asm volatile("ld.acquire.gpu.global.u32 %0, [%1];" : "=r"(v) : "l"(p) : "memory");
        } while (v < (uint32_t)nc);
    }
    __syncthreads();
}

__global__ void init_k(){
    int i = blockIdx.x*blockDim.x + threadIdx.x;
    if (i < Bn*Hn){
        g_h[0][i]=0.f; g_h[1][i]=0.f; g_c[i]=0.f;
        g_h16[0][i]=__float2half(0.f); g_h16[1][i]=__float2half(0.f);
    }
    if (i < Bn*2) g_inp[i]=0;
    if (i < 1152) g_bar[i]=0;
}

__global__ void pre_k(const float* __restrict__ Wh_e, const float* __restrict__ Wi_e,
                      const float* __restrict__ emb){
    int i = blockIdx.x*blockDim.x + threadIdx.x;
    if (i < 4*Hn*Hn) g_whe_h[i] = __float2half_rn(Wh_e[i]);
    if (i < 4*Hn*En) g_wie_r[i] = rna_f(Wi_e[i]);
    if (i < 1000*En) g_emb_r[i] = rna_f(emb[i]);
}

__global__ void post_k(const float* __restrict__ Wh_d, const float* __restrict__ Wi_d,
                       const float* __restrict__ act_emb, const float* __restrict__ tgt_emb,
                       const float* __restrict__ W_a, const float* __restrict__ W_t,
                       const float* __restrict__ Wf){
    int i = blockIdx.x*blockDim.x + threadIdx.x;
    if (i < 4*Hn*Hn) g_whd_h[i] = __float2half_rn(Wh_d[i]);
    if (i < 128*Hn){
        int r = i >> 9, k = i & 511;
        float v = 0.f;
        if (r < 8)        v = W_a[r*Hn + k];
        else if (r < 88)  v = W_t[(r-8)*Hn + k];
        else if (r == 88) v = Wf[k];
        g_wpad[i] = rna_f(v);
    }
    if (i < 88*4*Hn){
        int r = i >> 11, col = i & 2047;
        if (r < An){
            float a = 0.f; const float* w = Wi_d + col*64; const float* e = act_emb + r*EDn;
            #pragma unroll
            for (int k=0;k<EDn;k++) a += e[k]*w[k];
            g_act_z[r*4*Hn + col] = a;
        } else {
            int rr = r - An;
            float a = 0.f; const float* w = Wi_d + col*64 + EDn; const float* e = tgt_emb + rr*EDn;
            #pragma unroll
            for (int k=0;k<EDn;k++) a += e[k]*w[k];
            g_tgt_z[rr*4*Hn + col] = a;
        }
    }
}

// ---------------------------------------------------------------------------
// One-shot staged tf32 GEMMs (zx / proj).
// ---------------------------------------------------------------------------
template<int MODE>
__device__ __forceinline__ void gemm_tile(uint32_t* dsm, const float* __restrict__ Ap,
                                          int nIdx, int m0, float (&acc)[2][4][4])
{
    constexpr int NC = (MODE==0) ? 4 : 16;
    const int tid = threadIdx.x;
    const int lane = tid & 31, warp = tid >> 5;
    const int wm = warp >> 2, wn = warp & 3;
    const int c4 = lane & 3, r4 = lane >> 2;

    #pragma unroll
    for (int i=0;i<2;i++)
        #pragma unroll
        for (int j=0;j<4;j++)
            #pragma unroll
            for (int q=0;q<4;q++) acc[i][j][q]=0.f;

    auto aRow = [&](int m)->const float* {
        if (MODE==0){ int rr=m0+m; if (rr>999) rr=999; return Ap + (size_t)rr*En; }
        return Ap + (size_t)(m0+m)*Hn;
    };
    auto bRow = [&](int rn)->const float* {
        if (MODE==0) return g_wie_r + (size_t)(nIdx*128 + rn)*En;
        return g_wpad + (size_t)rn*Hn;
    };
    const uint32_t smb = smem_u32(dsm);
    auto load_chunk = [&](int c, int st){
        uint32_t base = smb + (uint32_t)st*24576u;
        int k0 = c*32;
        #pragma unroll
        for (int i=0;i<2;i++){
            int u = tid + i*256;
            int m = u>>3, g = u&7;
            CP_ASYNC16(base + (uint32_t)(m*128 + ((g^(m&7))<<4)), aRow(m) + k0 + g*4);
        }
        #pragma unroll
        for (int i=0;i<4;i++){
            int u = tid + i*256;
            int rn = u>>3, g = u&7;
            CP_ASYNC16(base + 8192u + (uint32_t)(rn*128 + ((g^(rn&7))<<4)), bRow(rn) + k0 + g*4);
        }
        CP_COMMIT();
    };

    load_chunk(0,0);
    load_chunk(1,1);

    #pragma unroll 1
    for (int c=0;c<NC;c++){
        if (c+2 < NC) load_chunk(c+2, (c+2)%3);
        if (c+2 < NC) { CP_WAIT(2); } else if (c+1 < NC) { CP_WAIT(1); } else { CP_WAIT(0); }
        __syncthreads();
        const uint32_t* S = dsm + (c%3)*6144;
        #pragma unroll
        for (int ks=0;ks<4;ks++){
            int sw0 = (((2*ks  ) ^ r4) << 2) + c4;
            int sw1 = (((2*ks+1) ^ r4) << 2) + c4;
            uint32_t a[2][4];
            #pragma unroll
            for (int i=0;i<2;i++){
                int r0 = (wm*32 + i*16 + r4)*32;
                a[i][0]=S[r0+sw0]; a[i][1]=S[r0+256+sw0];
                a[i][2]=S[r0+sw1]; a[i][3]=S[r0+256+sw1];
            }
            #pragma unroll
            for (int j=0;j<4;j++){
                int nb = wn*32 + j*8;
                int n0 = 2048 + (nb + r4)*32;
                uint32_t b0 = S[n0+sw0], b1 = S[n0+sw1];
                MMA_TF32(acc[0][j], a[0], b0, b1);
                MMA_TF32(acc[1][j], a[1], b0, b1);
            }
        }
        __syncthreads();
    }
}

__global__ __launch_bounds__(256,1) void zx_k(){
    extern __shared__ __align__(1024) uint32_t dsm[];
    const int nIdx = blockIdx.x;
    const int m0   = blockIdx.y * 64;
    const int lane = threadIdx.x & 31, warp = threadIdx.x >> 5;
    const int wm = warp >> 2, wn = warp & 3;
    const int c4 = lane & 3, r4 = lane >> 2;
    float acc[2][4][4];
    gemm_tile<0>(dsm, g_emb_r, nIdx, m0, acc);
    #pragma unroll
    for (int i=0;i<2;i++)
    #pragma unroll
    for (int rh=0;rh<2;rh++){
        int gm = m0 + wm*32 + i*16 + rh*8 + r4;
        if (gm >= 1000) continue;
        #pragma unroll
        for (int j=0;j<4;j++)
        #pragma unroll
        for (int cc=0;cc<2;cc++){
            int col = nIdx*128 + wn*32 + j*8 + c4*2 + cc;
            g_zx[(size_t)gm*2048 + col] = acc[i][j][rh*2+cc];
        }
    }
}

__global__ __launch_bounds__(256,1) void proj_k(){
    extern __shared__ __align__(1024) uint32_t dsm[];
    const int m0 = blockIdx.y * 64;
    const int lane = threadIdx.x & 31, warp = threadIdx.x >> 5;
    const int wm = warp >> 2, wn = warp & 3;
    const int c4 = lane & 3, r4 = lane >> 2;
    float acc[2][4][4];
    gemm_tile<3>(dsm, g_enc_out, 0, m0, acc);
    #pragma unroll
    for (int i=0;i<2;i++)
    #pragma unroll
    for (int rh=0;rh<2;rh++){
        int gm = m0 + wm*32 + i*16 + rh*8 + r4;   // gm = s*256 + b
        int s = gm >> 8, b = gm & 255;
        #pragma unroll
        for (int j=0;j<4;j++)
        #pragma unroll
        for (int cc=0;cc<2;cc++){
            int col = wn*32 + j*8 + c4*2 + cc;
            if (col < 96)
                g_P[((size_t)(b*96 + col))*Sn + s] = acc[i][j][rh*2+cc];
        }
    }
}

// ---------------------------------------------------------------------------
// Persistent step kernel — fp16 m16n8k16, whole-A-tile load (2 halves).
// smem: A 64KB @u32[0..16384) (chunk c at c*2048) ; B 64KB @u32[16384..32768).
// ---------------------------------------------------------------------------
template<int MODE>  // 1 = encoder, 2 = decoder
__global__ __launch_bounds__(256,1) void step_persist_k(
    const float* __restrict__ bias, const int* __restrict__ enc_input,
    const float* __restrict__ Wf, const float* __restrict__ bfv,
    const float* __restrict__ b_a, const float* __restrict__ b_t,
    float* __restrict__ out)
{
    extern __shared__ __align__(1024) uint32_t dsm[];
    __shared__ float shw[256], red[256], pp[256], shp[96];
    const int tid = threadIdx.x;
    const int lane = tid & 31, wid = tid >> 5;
    const int wm = wid >> 1, wn = wid & 1;
    const int c4 = lane & 3, r4 = lane >> 2;
    const int nIdx = blockIdx.x >> 2;
    const int mgrp = blockIdx.x & 3;
    const int m0   = mgrp * 64;
    const uint32_t smb = smem_u32(dsm);
    const int NSTEP = (MODE==1) ? Sn : Tn;

    // persistent fp16 weight slice: 8 chunks x (64 rows x 128B)
    {
        const __half* W16 = (MODE==1) ? g_whe_h : g_whd_h;
        #pragma unroll 1
        for (int ch=0; ch<8; ch++){
            #pragma unroll
            for (int i=0;i<2;i++){
                int u = tid + i*256;
                int rn = u>>3, g = u&7;
                int gate = rn>>4, ul = rn&15;
                const __half* src = W16 + (size_t)(gate*Hn + nIdx*16 + ul)*Hn + ch*64 + g*8;
                CP_ASYNC16(smb + 65536u + (uint32_t)(ch*8192 + rn*128 + ((g^(rn&7))<<4)), src);
            }
        }
        CP_COMMIT();
    }

    auto loadA = [&](const __half* hin, int c){
        uint32_t base = smb + (uint32_t)c*8192u;
        int k0 = c*64;
        #pragma unroll
        for (int i=0;i<2;i++){
            int u = tid + i*256;
            int m = u>>3, g = u&7;
            CP_ASYNC16(base + (uint32_t)(m*128 + ((g^(m&7))<<4)),
                       hin + (size_t)(m0+m)*Hn + k0 + g*8);
        }
    };

    float acc[4][4];

    #pragma unroll 1
    for (int t=0; t<NSTEP; t++){
        int par = t & 1;
        const __half* hin = g_h16[par];

        #pragma unroll
        for (int j=0;j<4;j++)
            #pragma unroll
            for (int q=0;q<4;q++) acc[j][q]=0.f;

        // load whole A tile as two 32KB halves
        #pragma unroll
        for (int c=0;c<4;c++) loadA(hin, c);
        CP_COMMIT();
        #pragma unroll
        for (int c=4;c<8;c++) loadA(hin, c);
        CP_COMMIT();

        #pragma unroll 1
        for (int c=0;c<8;c++){
            if (c==0){ CP_WAIT(1); __syncthreads(); }
            if (c==4){ CP_WAIT(0); __syncthreads(); }
            const uint32_t* SA = dsm + c*2048;
            const uint32_t* SB = dsm + 16384 + c*2048;
            #pragma unroll
            for (int ks=0;ks<4;ks++){
                int w0 = ks*8 + c4, w1 = w0 + 4;
                int rA0 = wm*16 + r4, rA1 = rA0 + 8;
                uint32_t a0 = SA[sidx(rA0,w0)], a1 = SA[sidx(rA1,w0)];
                uint32_t a2 = SA[sidx(rA0,w1)], a3 = SA[sidx(rA1,w1)];
                #pragma unroll
                for (int j=0;j<4;j++){
                    int cb = j*16 + wn*8 + r4;
                    uint32_t b0 = SB[sidx(cb,w0)], b1 = SB[sidx(cb,w1)];
                    MMA_F16(acc[j], a0,a1,a2,a3, b0,b1);
                }
            }
        }

        // LSTM epilogue
        #pragma unroll
        for (int rh=0;rh<2;rh++){
            int bg = m0 + wm*16 + rh*8 + r4;
            const float *x0, *x1 = nullptr;
            if (MODE==1){ x0 = g_zx + (size_t)enc_input[bg*Sn + t]*2048; }
            else { x0 = g_act_z + (size_t)g_inp[bg*2]*2048;
                   x1 = g_tgt_z + (size_t)g_inp[bg*2+1]*2048; }
            __half* hout16 = g_h16[par^1] + (size_t)bg*Hn;
            float*  crow   = g_c + (size_t)bg*Hn;
            float*  eout   = g_enc_out + ((size_t)t*Bn + bg)*Hn;
            float*  houtf  = g_h[par^1] + (size_t)bg*Hn;
            #pragma unroll
            for (int cc=0;cc<2;cc++){
                int u = nIdx*16 + wn*8 + c4*2 + cc;
                int q = rh*2 + cc;
                float xi, xf, xg, xo;
                if (MODE==1){ xi=x0[u]; xf=x0[512+u]; xg=x0[1024+u]; xo=x0[1536+u]; }
                else { xi=x0[u]+x1[u]; xf=x0[512+u]+x1[512+u];
                       xg=x0[1024+u]+x1[1024+u]; xo=x0[1536+u]+x1[1536+u]; }
                float zi = acc[0][q] + bias[       u] + xi;
                float zf = acc[1][q] + bias[ 512 + u] + xf;
                float zg = acc[2][q] + bias[1024 + u] + xg;
                float zo = acc[3][q] + bias[1536 + u] + xo;
                float co = crow[u];
                float cn = sigmoidf_(zf)*co + sigmoidf_(zi)*tanhf(zg);
                crow[u] = cn;
                __half hh = __float2half_rn(sigmoidf_(zo)*tanhf(cn));
                float  hn = __half2float(hh);
                hout16[u] = hh;
                if (MODE==1) eout[u] = hn;
                else         houtf[u] = hn;
            }
        }

        if (MODE==1){
            gbar(mgrp*256 + t, 32);
        } else {
            gbar(1024 + 2*t, 128);
            #pragma unroll 1
            for (int rb=0;rb<2;rb++){
                int b = blockIdx.x*2 + rb;
                const float* h = g_h[par^1] + (size_t)b*Hn;

                float part = h[tid]*Wf[512+tid] + h[tid+256]*Wf[768+tid];
                red[tid] = part; __syncthreads();
                for (int o=128;o;o>>=1){ if (tid<o) red[tid]+=red[tid+o]; __syncthreads(); }
                float hdot = red[0] + bfv[0];
                __syncthreads();

                float sc = g_P[((size_t)(b*96 + 88))*Sn + tid] + hdot;
                red[tid] = sc; __syncthreads();
                for (int o=128;o;o>>=1){ if (tid<o) red[tid]=fmaxf(red[tid],red[tid+o]); __syncthreads(); }
                float m = red[0]; __syncthreads();
                float e = expf(sc - m);
                red[tid] = e; __syncthreads();
                for (int o=128;o;o>>=1){ if (tid<o) red[tid]+=red[tid+o]; __syncthreads(); }
                float inv = 1.f/red[0];
                shw[tid] = e*inv;
                __syncthreads();

                if (tid < 176){
                    int col = tid >> 1, hf = tid & 1;
                    const float* pb = g_P + (size_t)(b*96 + col)*Sn + hf*128;
                    const float* wv = shw + hf*128;
                    float a0=0.f,a1=0.f,a2=0.f,a3=0.f;
                    #pragma unroll 8
                    for (int s=0; s<128; s+=4){
                        a0 += wv[s  ]*pb[s  ];
                        a1 += wv[s+1]*pb[s+1];
                        a2 += wv[s+2]*pb[s+2];
                        a3 += wv[s+3]*pb[s+3];
                    }
                    pp[tid] = (a0+a1)+(a2+a3);
                }
                __syncthreads();
                if (tid < 88){
                    float v = pp[2*tid] + pp[2*tid+1] + ((tid < An) ? b_a[tid] : b_t[tid-An]);
                    shp[tid] = v;
                    if (tid < An) out[(b*Tn + t)*An + tid] = v;
                    else          out[Bn*Tn*An + (b*Tn + t)*NTn + (tid-An)] = v;
                }
                __syncthreads();
                if (tid == 0){
                    int ia=0; float bv=shp[0];
                    #pragma unroll
                    for (int a=1;a<An;a++) if (shp[a]>bv){bv=shp[a]; ia=a;}
                    int it=0; float tv=shp[An];
                    for (int j=1;j<NTn;j++) if (shp[An+j]>tv){tv=shp[An+j]; it=j;}
                    g_inp[b*2] = ia; g_inp[b*2+1] = it;
                }
                __syncthreads();
            }
            gbar(1024 + 2*t + 1, 128);
        }
    }
}

extern "C" void kernel_launch(void* const* d_in, const int* in_sizes, int n_in,
                              void* d_out, int out_size)
{
    const int*   enc_input = (const int*)  d_in[0];
    const float* enc_embed = (const float*)d_in[2];
    const float* Wi_e      = (const float*)d_in[3];
    const float* Wh_e      = (const float*)d_in[4];
    const float* b_e       = (const float*)d_in[5];
    const float* act_emb   = (const float*)d_in[6];
    const float* tgt_emb   = (const float*)d_in[7];
    const float* Wi_d      = (const float*)d_in[8];
    const float* Wh_d      = (const float*)d_in[9];
    const float* b_d       = (const float*)d_in[10];
    const float* W_a       = (const float*)d_in[11];
    const float* b_a       = (const float*)d_in[12];
    const float* W_t       = (const float*)d_in[13];
    const float* b_t       = (const float*)d_in[14];
    const float* Wf        = (const float*)d_in[15];
    const float* bf        = (const float*)d_in[16];
    float* out = (float*)d_out;

    const int GEMM_SMEM = 3*24576;
    const int STEP_SMEM = 65536 + 65536;   // A 64KB + B 64KB
    cudaFuncSetAttribute(zx_k,   cudaFuncAttributeMaxDynamicSharedMemorySize, GEMM_SMEM);
    cudaFuncSetAttribute(proj_k, cudaFuncAttributeMaxDynamicSharedMemorySize, GEMM_SMEM);
    cudaFuncSetAttribute(step_persist_k<1>, cudaFuncAttributeMaxDynamicSharedMemorySize, STEP_SMEM);
    cudaFuncSetAttribute(step_persist_k<2>, cudaFuncAttributeMaxDynamicSharedMemorySize, STEP_SMEM);

    init_k<<<(Bn*Hn + 255)/256, 256>>>();                                   // 0
    pre_k<<<4096, 256>>>(Wh_e, Wi_e, enc_embed);                            // 1
    zx_k<<<dim3(16,16), 256, GEMM_SMEM>>>();                                // 2
    step_persist_k<1><<<128, 256, STEP_SMEM>>>(b_e, enc_input, nullptr,     // 3
                                               nullptr, nullptr, nullptr, nullptr);
    post_k<<<4096, 256>>>(Wh_d, Wi_d, act_emb, tgt_emb, W_a, W_t, Wf);      // 4
    proj_k<<<dim3(1,1024), 256, GEMM_SMEM>>>();                             // 5
    step_persist_k<2><<<128, 256, STEP_SMEM>>>(b_d, nullptr, Wf, bf,        // 6
                                               b_a, b_t, out);
}